// round 10
// baseline (speedup 1.0000x reference)
#include <cuda_runtime.h>
#include <cstdint>

#define TOT    400000
#define NPTS   50000
#define NBLK   5
#define PTS    128          // points per CTA
#define THR    128          // threads per CTA
#define XSTR   68           // activation row stride (floats)

typedef unsigned long long ull;

// Per-batch conditioning: cond[b][i][h] = task_feature[b] @ fc_c_W[i][64:576,:] + fc_c_b[i]
__device__ float g_cond[8 * NBLK * 64];

// ---------- packed f32x2 helpers ----------
__device__ __forceinline__ ull dup2(float x) {
    ull r; asm("mov.b64 %0, {%1, %1};" : "=l"(r) : "f"(x)); return r;
}
__device__ __forceinline__ float2 unpk(ull a) {
    float2 f; asm("mov.b64 {%0, %1}, %2;" : "=f"(f.x), "=f"(f.y) : "l"(a)); return f;
}
__device__ __forceinline__ void fma2(ull &a, ull x, ull w) {
    asm("fma.rn.f32x2 %0, %1, %2, %0;" : "+l"(a) : "l"(x), "l"(w));
}
__device__ __forceinline__ void add2(ull &a, ull b) {
    asm("add.rn.f32x2 %0, %0, %1;" : "+l"(a) : "l"(b));
}

// ---------- cp.async helpers ----------
__device__ __forceinline__ void cpa16(uint32_t dst, const float* src) {
    asm volatile("cp.async.cg.shared.global [%0], [%1], 16;" :: "r"(dst), "l"(src));
}
__device__ __forceinline__ void cpa_commit() {
    asm volatile("cp.async.commit_group;");
}
template<int N> __device__ __forceinline__ void cpa_wait() {
    asm volatile("cp.async.wait_group %0;" :: "n"(N));
}

// 16KB weight tile (64x64 f32): 8 x 16B per thread (128 threads)
__device__ __forceinline__ void load_w16(float* dst, const float* src, int tid) {
    uint32_t d = (uint32_t)__cvta_generic_to_shared(dst);
    #pragma unroll
    for (int t = 0; t < 8; t++) {
        int w = tid + t * THR;
        cpa16(d + w * 16, src + w * 4);
    }
}
// 32KB codes -> X (128 rows x XSTR): 16 x 16B per thread
__device__ __forceinline__ void load_codes(float* X, const float* src, int tid) {
    uint32_t d = (uint32_t)__cvta_generic_to_shared(X);
    #pragma unroll
    for (int t = 0; t < 16; t++) {
        int w = tid + t * THR;
        int pt = w >> 4, e = w & 15;
        cpa16(d + (pt * XSTR + e * 4) * 4, src + w * 4);
    }
}

// ---------- shared layout (float offsets) ----------
#define OFF_WA    0        // 4096
#define OFF_WB    4096     // 4096
#define OFF_NET   8192     // 128*68 = 8704
#define OFF_X     16896    // 8704 (codes OR relu(h))
#define OFF_OW    25600    // 768
#define OFF_OB    26368    // 16 (12 + pad)
#define OFF_PW    26384    // 192
#define OFF_PB    26576    // 64
#define OFF_CND   26640    // 2 * 320 (cond rows for this CTA's <=2 batches)
#define OFF_B0    27280    // 5*64
#define OFF_B1    27600    // 5*64
#define SM_FLOATS 27920
#define SM_BYTES  (SM_FLOATS * 4)   // 111680 B -> 2 CTAs/SM

// ---------- conditioning precompute ----------
__global__ void cond_kernel(const float* __restrict__ tf,
                            const float* __restrict__ fc_c_W,
                            const float* __restrict__ fc_c_b) {
    int bi = blockIdx.x;          // b*5 + i
    int b  = bi / NBLK, i = bi % NBLK;
    int h  = threadIdx.x & 63, g = threadIdx.x >> 6;
    const float* W = fc_c_W + (size_t)i * 576 * 64 + 64 * 64 + h;
    const float* t = tf + b * 512;
    float acc = 0.f;
    int k0 = g * 128;
    #pragma unroll 8
    for (int k = k0; k < k0 + 128; k++) acc += t[k] * W[(size_t)k * 64];
    __shared__ float red[256];
    red[threadIdx.x] = acc;
    __syncthreads();
    if (g == 0) {
        float s = red[h] + red[h + 64] + red[h + 128] + red[h + 192] + fc_c_b[i * 64 + h];
        g_cond[bi * 64 + h] = s;
    }
}

// GEMM microtile: 8 points (rows pg+16q) x 8 cols ({og*4..+3}, {32+og*4..+3})
// BOTH x and w double-buffered one kk-chunk ahead: every LDS has a full
// 128-fma2 burst of independent work behind it.
__device__ __forceinline__ void mm64(ull acc[8][4], const float* __restrict__ xb,
                                     const float* __restrict__ Wt, bool relu_x) {
    float xa[2][8][4];
    ulonglong2 wv[2][4][2];
    #pragma unroll
    for (int q = 0; q < 8; q++)
        *(float4*)xa[0][q] = *(const float4*)(xb + q * 16 * XSTR);
    #pragma unroll
    for (int d = 0; d < 4; d++) {
        wv[0][d][0] = *(const ulonglong2*)(Wt + d * 64);
        wv[0][d][1] = *(const ulonglong2*)(Wt + d * 64 + 32);
    }
    #pragma unroll 2
    for (int kc = 0; kc < 16; kc++) {
        const int cur = kc & 1, nxt = cur ^ 1;
        if (kc < 15) {
            #pragma unroll
            for (int q = 0; q < 8; q++)
                *(float4*)xa[nxt][q] = *(const float4*)(xb + q * 16 * XSTR + (kc + 1) * 4);
            #pragma unroll
            for (int d = 0; d < 4; d++) {
                wv[nxt][d][0] = *(const ulonglong2*)(Wt + ((kc + 1) * 4 + d) * 64);
                wv[nxt][d][1] = *(const ulonglong2*)(Wt + ((kc + 1) * 4 + d) * 64 + 32);
            }
        }
        #pragma unroll
        for (int d = 0; d < 4; d++) {
            #pragma unroll
            for (int q = 0; q < 8; q++) {
                float xv = xa[cur][q][d];
                if (relu_x) xv = fmaxf(xv, 0.f);
                ull xd = dup2(xv);
                fma2(acc[q][0], xd, wv[cur][d][0].x);
                fma2(acc[q][1], xd, wv[cur][d][0].y);
                fma2(acc[q][2], xd, wv[cur][d][1].x);
                fma2(acc[q][3], xd, wv[cur][d][1].y);
            }
        }
    }
}

__global__ __launch_bounds__(THR, 2)
void mlp_kernel(const float* __restrict__ p, const float* __restrict__ c,
                const float* __restrict__ fc_p_W, const float* __restrict__ fc_p_b,
                const float* __restrict__ fc_c_W,
                const float* __restrict__ blk0_W, const float* __restrict__ blk0_b,
                const float* __restrict__ blk1_W, const float* __restrict__ blk1_b,
                const float* __restrict__ fc_out_W, const float* __restrict__ fc_out_b,
                float* __restrict__ out) {
    extern __shared__ float sm[];
    const int tid = threadIdx.x;
    const int og  = tid & 7;          // cols og*4..+3 and 32+og*4..+3
    const int pg  = tid >> 3;         // rows pg + 16q, q=0..7
    const int base = blockIdx.x * PTS;
    const int bA_id = base / NPTS;
    const int bB_id = (base + PTS - 1) / NPTS;

    float* WA   = sm + OFF_WA;
    float* WB   = sm + OFF_WB;
    float* NETB = sm + OFF_NET;
    float* X    = sm + OFF_X;

    // prologue async: Wc_0 -> WA (group), codes -> X (group)
    load_w16(WA, fc_c_W, tid); cpa_commit();
    load_codes(X, c + (size_t)base * 64, tid); cpa_commit();

    // one-time small operands -> smem (strided over full range; THR=128)
    for (int w = tid; w < 768; w += THR) sm[OFF_OW + w] = fc_out_W[w];
    if (tid < 16) sm[OFF_OB + tid] = (tid < 12) ? fc_out_b[tid] : 0.f;
    for (int w = tid; w < 192; w += THR) sm[OFF_PW + w] = fc_p_W[w];
    for (int w = tid; w < 64; w += THR) sm[OFF_PB + w] = fc_p_b[w];
    for (int w = tid; w < 640; w += THR) {          // cond rows for batches bA/bB
        int sel = w / 320, r = w % 320;
        sm[OFF_CND + w] = g_cond[(sel ? bB_id : bA_id) * 320 + r];
    }
    for (int w = tid; w < 320; w += THR) {
        sm[OFF_B0 + w] = blk0_b[w];
        sm[OFF_B1 + w] = blk1_b[w];
    }
    __syncthreads();   // smem params visible (cp.async groups still in flight)

    float* wrN = NETB + pg * XSTR + og * 4;      // own net tile
    float* wrX = X    + pg * XSTR + og * 4;      // own h tile
    const float* xb = X    + pg * XSTR;
    const float* nb = NETB + pg * XSTR;

    // per-row cond smem offsets
    int cnd[8];
    #pragma unroll
    for (int q = 0; q < 8; q++) {
        int sel = ((base + pg + q * 16) / NPTS == bB_id) ? 1 : 0;
        cnd[q] = OFF_CND + sel * 320 + og * 4;
    }

    // ---- p-layer: net0 = p @ Wp + bp -> NETB (own tile) ----
    {
        ulonglong2 bA = *(const ulonglong2*)(sm + OFF_PB + og * 4);
        ulonglong2 bB = *(const ulonglong2*)(sm + OFF_PB + og * 4 + 32);
        ulonglong2 w[3][2];
        #pragma unroll
        for (int e = 0; e < 3; e++) {
            w[e][0] = *(const ulonglong2*)(sm + OFF_PW + e * 64 + og * 4);
            w[e][1] = *(const ulonglong2*)(sm + OFF_PW + e * 64 + og * 4 + 32);
        }
        #pragma unroll
        for (int q = 0; q < 8; q++) {
            int pt = base + pg + q * 16;
            ull a0 = bA.x, a1 = bA.y, a2 = bB.x, a3 = bB.y;
            #pragma unroll
            for (int e = 0; e < 3; e++) {
                ull xd = dup2(__ldg(p + (size_t)pt * 3 + e));
                fma2(a0, xd, w[e][0].x); fma2(a1, xd, w[e][0].y);
                fma2(a2, xd, w[e][1].x); fma2(a3, xd, w[e][1].y);
            }
            ulonglong2 s0, s1; s0.x = a0; s0.y = a1; s1.x = a2; s1.y = a3;
            *(ulonglong2*)(wrN + q * 16 * XSTR)      = s0;
            *(ulonglong2*)(wrN + q * 16 * XSTR + 32) = s1;
        }
    }

    for (int i = 0; i < NBLK; i++) {
        float* Wcur = (i & 1) ? WB : WA;
        float* Woth = (i & 1) ? WA : WB;

        if (i > 0) { load_codes(X, c + (size_t)base * 64, tid); cpa_commit(); }
        load_w16(Woth, blk0_W + (size_t)i * 4096, tid); cpa_commit();
        cpa_wait<1>();            // Wc_i + codes done; W0 still in flight
        __syncthreads();

        ull acc[8][4];
        // ---- step1: net = net + cond + c @ Wc ----
        #pragma unroll
        for (int q = 0; q < 8; q++) {
            ulonglong2 a = *(const ulonglong2*)(wrN + q * 16 * XSTR);
            ulonglong2 b = *(const ulonglong2*)(wrN + q * 16 * XSTR + 32);
            ulonglong2 c0 = *(const ulonglong2*)(sm + cnd[q] + i * 64);
            ulonglong2 c1 = *(const ulonglong2*)(sm + cnd[q] + i * 64 + 32);
            acc[q][0] = a.x; acc[q][1] = a.y; acc[q][2] = b.x; acc[q][3] = b.y;
            add2(acc[q][0], c0.x); add2(acc[q][1], c0.y);
            add2(acc[q][2], c1.x); add2(acc[q][3], c1.y);
        }
        mm64(acc, xb, Wcur + og * 4, false);
        #pragma unroll
        for (int q = 0; q < 8; q++) {
            ulonglong2 s0, s1;
            s0.x = acc[q][0]; s0.y = acc[q][1]; s1.x = acc[q][2]; s1.y = acc[q][3];
            *(ulonglong2*)(wrN + q * 16 * XSTR)      = s0;
            *(ulonglong2*)(wrN + q * 16 * XSTR + 32) = s1;
        }
        cpa_wait<0>();            // W0 arrived
        __syncthreads();

        // ---- step2: h = relu(net) @ W0 + b0 ; relu(h) -> X ----
        load_w16(Wcur, blk1_W + (size_t)i * 4096, tid); cpa_commit();  // W1 prefetch
        {
            ulonglong2 bA = *(const ulonglong2*)(sm + OFF_B0 + i * 64 + og * 4);
            ulonglong2 bB = *(const ulonglong2*)(sm + OFF_B0 + i * 64 + og * 4 + 32);
            #pragma unroll
            for (int q = 0; q < 8; q++) {
                acc[q][0] = bA.x; acc[q][1] = bA.y; acc[q][2] = bB.x; acc[q][3] = bB.y;
            }
            mm64(acc, nb, Woth + og * 4, true);
            #pragma unroll
            for (int q = 0; q < 8; q++) {
                float2 f0 = unpk(acc[q][0]), f1 = unpk(acc[q][1]);
                float2 f2 = unpk(acc[q][2]), f3 = unpk(acc[q][3]);
                *(float4*)(wrX + q * 16 * XSTR) =
                    make_float4(fmaxf(f0.x, 0.f), fmaxf(f0.y, 0.f),
                                fmaxf(f1.x, 0.f), fmaxf(f1.y, 0.f));
                *(float4*)(wrX + q * 16 * XSTR + 32) =
                    make_float4(fmaxf(f2.x, 0.f), fmaxf(f2.y, 0.f),
                                fmaxf(f3.x, 0.f), fmaxf(f3.y, 0.f));
            }
        }
        cpa_wait<0>();            // W1 arrived
        __syncthreads();

        // ---- step3: net += relu(h) @ W1 + b1 ----
        if (i < NBLK - 1) { load_w16(Woth, fc_c_W + (size_t)(i + 1) * 576 * 64, tid); cpa_commit(); }
        {
            ulonglong2 bA = *(const ulonglong2*)(sm + OFF_B1 + i * 64 + og * 4);
            ulonglong2 bB = *(const ulonglong2*)(sm + OFF_B1 + i * 64 + og * 4 + 32);
            #pragma unroll
            for (int q = 0; q < 8; q++) {
                ulonglong2 a = *(const ulonglong2*)(wrN + q * 16 * XSTR);
                ulonglong2 b = *(const ulonglong2*)(wrN + q * 16 * XSTR + 32);
                acc[q][0] = a.x; acc[q][1] = a.y; acc[q][2] = b.x; acc[q][3] = b.y;
                add2(acc[q][0], bA.x); add2(acc[q][1], bA.y);
                add2(acc[q][2], bB.x); add2(acc[q][3], bB.y);
            }
            mm64(acc, xb, Wcur + og * 4, false);
            #pragma unroll
            for (int q = 0; q < 8; q++) {
                ulonglong2 s0, s1;
                s0.x = acc[q][0]; s0.y = acc[q][1]; s1.x = acc[q][2]; s1.y = acc[q][3];
                *(ulonglong2*)(wrN + q * 16 * XSTR)      = s0;
                *(ulonglong2*)(wrN + q * 16 * XSTR + 32) = s1;
            }
        }
        __syncthreads();
    }

    // ---- out = relu(net) @ fc_out_W + fc_out_b ; one point per thread ----
    {
        ull o[6];
        const ull* ob = (const ull*)(sm + OFF_OB);
        #pragma unroll
        for (int j = 0; j < 6; j++) o[j] = ob[j];
        const float* xr = NETB + tid * XSTR;
        #pragma unroll 2
        for (int kk = 0; kk < 64; kk += 4) {
            float xa[4];
            *(float4*)xa = *(const float4*)(xr + kk);
            #pragma unroll
            for (int d = 0; d < 4; d++) {
                ull xd = dup2(fmaxf(xa[d], 0.f));
                const ull* wr = (const ull*)(sm + OFF_OW + (kk + d) * 12);
                #pragma unroll
                for (int j = 0; j < 6; j++) fma2(o[j], xd, wr[j]);
            }
        }
        float2 f0 = unpk(o[0]), f1 = unpk(o[1]), f2 = unpk(o[2]);
        float2 f3 = unpk(o[3]), f4 = unpk(o[4]), f5 = unpk(o[5]);
        float4* dst = (float4*)(out + (size_t)(base + tid) * 12);
        dst[0] = make_float4(f0.x, f0.y, f1.x, f1.y);
        dst[1] = make_float4(f2.x, f2.y, f3.x, f3.y);
        dst[2] = make_float4(f4.x, f4.y, f5.x, f5.y);
    }
}

extern "C" void kernel_launch(void* const* d_in, const int* in_sizes, int n_in,
                              void* d_out, int out_size) {
    const float* p        = (const float*)d_in[0];
    const float* c        = (const float*)d_in[1];
    const float* tf       = (const float*)d_in[2];
    const float* fc_p_W   = (const float*)d_in[3];
    const float* fc_p_b   = (const float*)d_in[4];
    const float* fc_c_W   = (const float*)d_in[5];
    const float* fc_c_b   = (const float*)d_in[6];
    const float* blk0_W   = (const float*)d_in[7];
    const float* blk0_b   = (const float*)d_in[8];
    const float* blk1_W   = (const float*)d_in[9];
    const float* blk1_b   = (const float*)d_in[10];
    const float* fc_out_W = (const float*)d_in[11];
    const float* fc_out_b = (const float*)d_in[12];
    float* out = (float*)d_out;

    cudaFuncSetAttribute(mlp_kernel, cudaFuncAttributeMaxDynamicSharedMemorySize, SM_BYTES);

    cond_kernel<<<8 * NBLK, 256>>>(tf, fc_c_W, fc_c_b);

    int grid = TOT / PTS;   // 3125 CTAs
    mlp_kernel<<<grid, THR, SM_BYTES>>>(p, c, fc_p_W, fc_p_b, fc_c_W,
                                        blk0_W, blk0_b, blk1_W, blk1_b,
                                        fc_out_W, fc_out_b, out);
}

// round 11
// speedup vs baseline: 1.0017x; 1.0017x over previous
#include <cuda_runtime.h>
#include <cstdint>

#define TOT    400000
#define NPTS   50000
#define NBLK   5
#define PTS    128          // points per CTA
#define THR    128          // threads per CTA
#define XSTR   68           // activation row stride (floats)

typedef unsigned long long ull;

// Per-batch conditioning: cond[b][i][h] = task_feature[b] @ fc_c_W[i][64:576,:] + fc_c_b[i]
__device__ float g_cond[8 * NBLK * 64];

// ---------- packed f32x2 helpers ----------
__device__ __forceinline__ ull dup2(float x) {
    ull r; asm("mov.b64 %0, {%1, %1};" : "=l"(r) : "f"(x)); return r;
}
__device__ __forceinline__ float2 unpk(ull a) {
    float2 f; asm("mov.b64 {%0, %1}, %2;" : "=f"(f.x), "=f"(f.y) : "l"(a)); return f;
}
__device__ __forceinline__ void fma2(ull &a, ull x, ull w) {
    asm("fma.rn.f32x2 %0, %1, %2, %0;" : "+l"(a) : "l"(x), "l"(w));
}
__device__ __forceinline__ void add2(ull &a, ull b) {
    asm("add.rn.f32x2 %0, %0, %1;" : "+l"(a) : "l"(b));
}

// ---------- cp.async helpers (codes prologue only) ----------
__device__ __forceinline__ void cpa16(uint32_t dst, const float* src) {
    asm volatile("cp.async.cg.shared.global [%0], [%1], 16;" :: "r"(dst), "l"(src));
}
__device__ __forceinline__ void cpa_commit() {
    asm volatile("cp.async.commit_group;");
}
template<int N> __device__ __forceinline__ void cpa_wait() {
    asm volatile("cp.async.wait_group %0;" :: "n"(N));
}

// 32KB codes -> CODES (128 rows x XSTR): 16 x 16B per thread
__device__ __forceinline__ void load_codes(float* X, const float* src, int tid) {
    uint32_t d = (uint32_t)__cvta_generic_to_shared(X);
    #pragma unroll
    for (int t = 0; t < 16; t++) {
        int w = tid + t * THR;
        int pt = w >> 4, e = w & 15;
        cpa16(d + (pt * XSTR + e * 4) * 4, src + w * 4);
    }
}

// ---------- shared layout (float offsets) ----------
#define OFF_CODES 0        // 8704 (persistent: point codes)
#define OFF_NET   8704     // 8704
#define OFF_H     17408    // 8704
#define OFF_OW    26112    // 768
#define OFF_OB    26880    // 16
#define OFF_PW    26896    // 192
#define OFF_PB    27088    // 64
#define OFF_CND   27152    // 640 (cond rows for this CTA's <=2 batches)
#define OFF_B0    27792    // 320
#define OFF_B1    28112    // 320
#define SM_FLOATS 28432
#define SM_BYTES  (SM_FLOATS * 4)   // 113728 B -> 2 CTAs/SM

// ---------- conditioning precompute ----------
__global__ void cond_kernel(const float* __restrict__ tf,
                            const float* __restrict__ fc_c_W,
                            const float* __restrict__ fc_c_b) {
    int bi = blockIdx.x;          // b*5 + i
    int b  = bi / NBLK, i = bi % NBLK;
    int h  = threadIdx.x & 63, g = threadIdx.x >> 6;
    const float* W = fc_c_W + (size_t)i * 576 * 64 + 64 * 64 + h;
    const float* t = tf + b * 512;
    float acc = 0.f;
    int k0 = g * 128;
    #pragma unroll 8
    for (int k = k0; k < k0 + 128; k++) acc += t[k] * W[(size_t)k * 64];
    __shared__ float red[256];
    red[threadIdx.x] = acc;
    __syncthreads();
    if (g == 0) {
        float s = red[h] + red[h + 64] + red[h + 128] + red[h + 192] + fc_c_b[i * 64 + h];
        g_cond[bi * 64 + h] = s;
    }
}

// GEMM microtile: 8 points (rows pg+16q) x 8 cols ({og*4..+3}, {32+og*4..+3})
// x from smem, w from GLOBAL (L1/L2-cached, broadcast) — both one chunk ahead.
__device__ __forceinline__ void mm64g(ull acc[8][4], const float* __restrict__ xb,
                                      const float* __restrict__ Wg, bool relu_x) {
    float xa[2][8][4];
    ulonglong2 wv[2][4][2];
    #pragma unroll
    for (int q = 0; q < 8; q++)
        *(float4*)xa[0][q] = *(const float4*)(xb + q * 16 * XSTR);
    #pragma unroll
    for (int d = 0; d < 4; d++) {
        wv[0][d][0] = __ldg((const ulonglong2*)(Wg + d * 64));
        wv[0][d][1] = __ldg((const ulonglong2*)(Wg + d * 64 + 32));
    }
    #pragma unroll 2
    for (int kc = 0; kc < 16; kc++) {
        const int cur = kc & 1, nxt = cur ^ 1;
        if (kc < 15) {
            #pragma unroll
            for (int d = 0; d < 4; d++) {
                wv[nxt][d][0] = __ldg((const ulonglong2*)(Wg + ((kc + 1) * 4 + d) * 64));
                wv[nxt][d][1] = __ldg((const ulonglong2*)(Wg + ((kc + 1) * 4 + d) * 64 + 32));
            }
            #pragma unroll
            for (int q = 0; q < 8; q++)
                *(float4*)xa[nxt][q] = *(const float4*)(xb + q * 16 * XSTR + (kc + 1) * 4);
        }
        #pragma unroll
        for (int d = 0; d < 4; d++) {
            #pragma unroll
            for (int q = 0; q < 8; q++) {
                float xv = xa[cur][q][d];
                if (relu_x) xv = fmaxf(xv, 0.f);
                ull xd = dup2(xv);
                fma2(acc[q][0], xd, wv[cur][d][0].x);
                fma2(acc[q][1], xd, wv[cur][d][0].y);
                fma2(acc[q][2], xd, wv[cur][d][1].x);
                fma2(acc[q][3], xd, wv[cur][d][1].y);
            }
        }
    }
}

__global__ __launch_bounds__(THR, 2)
void mlp_kernel(const float* __restrict__ p, const float* __restrict__ c,
                const float* __restrict__ fc_p_W, const float* __restrict__ fc_p_b,
                const float* __restrict__ fc_c_W,
                const float* __restrict__ blk0_W, const float* __restrict__ blk0_b,
                const float* __restrict__ blk1_W, const float* __restrict__ blk1_b,
                const float* __restrict__ fc_out_W, const float* __restrict__ fc_out_b,
                float* __restrict__ out) {
    extern __shared__ float sm[];
    const int tid = threadIdx.x;
    const int og  = tid & 7;          // cols og*4..+3 and 32+og*4..+3
    const int pg  = tid >> 3;         // rows pg + 16q, q=0..7
    const int base = blockIdx.x * PTS;
    const int bA_id = base / NPTS;
    const int bB_id = (base + PTS - 1) / NPTS;

    float* CODES = sm + OFF_CODES;
    float* NETB  = sm + OFF_NET;
    float* H     = sm + OFF_H;

    // prologue: codes -> smem (once, persistent)
    load_codes(CODES, c + (size_t)base * 64, tid); cpa_commit();

    // one-time small operands -> smem
    for (int w = tid; w < 768; w += THR) sm[OFF_OW + w] = fc_out_W[w];
    if (tid < 16) sm[OFF_OB + tid] = (tid < 12) ? fc_out_b[tid] : 0.f;
    for (int w = tid; w < 192; w += THR) sm[OFF_PW + w] = fc_p_W[w];
    for (int w = tid; w < 64; w += THR) sm[OFF_PB + w] = fc_p_b[w];
    for (int w = tid; w < 640; w += THR) {          // cond rows for batches bA/bB
        int sel = w / 320, r = w % 320;
        sm[OFF_CND + w] = g_cond[(sel ? bB_id : bA_id) * 320 + r];
    }
    for (int w = tid; w < 320; w += THR) {
        sm[OFF_B0 + w] = blk0_b[w];
        sm[OFF_B1 + w] = blk1_b[w];
    }
    cpa_wait<0>();
    __syncthreads();   // barrier #1 (only other one is before the epilogue)

    float* wrN = NETB + pg * XSTR + og * 4;      // own net tile
    float* wrH = H    + pg * XSTR + og * 4;      // own h tile
    const float* xc = CODES + pg * XSTR;
    const float* xn = NETB  + pg * XSTR;
    const float* xh = H     + pg * XSTR;

    // per-row cond smem offsets
    int cnd[8];
    #pragma unroll
    for (int q = 0; q < 8; q++) {
        int sel = ((base + pg + q * 16) / NPTS == bB_id) ? 1 : 0;
        cnd[q] = OFF_CND + sel * 320 + og * 4;
    }

    // ---- p-layer: net0 = p @ Wp + bp -> NETB (own tile) ----
    {
        ulonglong2 bA = *(const ulonglong2*)(sm + OFF_PB + og * 4);
        ulonglong2 bB = *(const ulonglong2*)(sm + OFF_PB + og * 4 + 32);
        ulonglong2 w[3][2];
        #pragma unroll
        for (int e = 0; e < 3; e++) {
            w[e][0] = *(const ulonglong2*)(sm + OFF_PW + e * 64 + og * 4);
            w[e][1] = *(const ulonglong2*)(sm + OFF_PW + e * 64 + og * 4 + 32);
        }
        #pragma unroll
        for (int q = 0; q < 8; q++) {
            int pt = base + pg + q * 16;
            ull a0 = bA.x, a1 = bA.y, a2 = bB.x, a3 = bB.y;
            #pragma unroll
            for (int e = 0; e < 3; e++) {
                ull xd = dup2(__ldg(p + (size_t)pt * 3 + e));
                fma2(a0, xd, w[e][0].x); fma2(a1, xd, w[e][0].y);
                fma2(a2, xd, w[e][1].x); fma2(a3, xd, w[e][1].y);
            }
            ulonglong2 s0, s1; s0.x = a0; s0.y = a1; s1.x = a2; s1.y = a3;
            *(ulonglong2*)(wrN + q * 16 * XSTR)      = s0;
            *(ulonglong2*)(wrN + q * 16 * XSTR + 32) = s1;
        }
    }
    __syncwarp();

    for (int i = 0; i < NBLK; i++) {
        const float* Wc_g = fc_c_W + (size_t)i * 576 * 64 + og * 4;  // rows 0..63 = c-part
        const float* W0_g = blk0_W + (size_t)i * 4096 + og * 4;
        const float* W1_g = blk1_W + (size_t)i * 4096 + og * 4;

        ull acc[8][4];
        // ---- step1: net = net + cond + c @ Wc ----
        #pragma unroll
        for (int q = 0; q < 8; q++) {
            ulonglong2 a = *(const ulonglong2*)(wrN + q * 16 * XSTR);
            ulonglong2 b = *(const ulonglong2*)(wrN + q * 16 * XSTR + 32);
            ulonglong2 c0 = *(const ulonglong2*)(sm + cnd[q] + i * 64);
            ulonglong2 c1 = *(const ulonglong2*)(sm + cnd[q] + i * 64 + 32);
            acc[q][0] = a.x; acc[q][1] = a.y; acc[q][2] = b.x; acc[q][3] = b.y;
            add2(acc[q][0], c0.x); add2(acc[q][1], c0.y);
            add2(acc[q][2], c1.x); add2(acc[q][3], c1.y);
        }
        mm64g(acc, xc, Wc_g, false);
        #pragma unroll
        for (int q = 0; q < 8; q++) {
            ulonglong2 s0, s1;
            s0.x = acc[q][0]; s0.y = acc[q][1]; s1.x = acc[q][2]; s1.y = acc[q][3];
            *(ulonglong2*)(wrN + q * 16 * XSTR)      = s0;
            *(ulonglong2*)(wrN + q * 16 * XSTR + 32) = s1;
        }
        __syncwarp();   // net exchange is warp-local (8-lane pg groups)

        // ---- step2: h = relu(net) @ W0 + b0 ; relu(h) -> H ----
        {
            ulonglong2 bA = *(const ulonglong2*)(sm + OFF_B0 + i * 64 + og * 4);
            ulonglong2 bB = *(const ulonglong2*)(sm + OFF_B0 + i * 64 + og * 4 + 32);
            #pragma unroll
            for (int q = 0; q < 8; q++) {
                acc[q][0] = bA.x; acc[q][1] = bA.y; acc[q][2] = bB.x; acc[q][3] = bB.y;
            }
            mm64g(acc, xn, W0_g, true);
            #pragma unroll
            for (int q = 0; q < 8; q++) {
                float2 f0 = unpk(acc[q][0]), f1 = unpk(acc[q][1]);
                float2 f2 = unpk(acc[q][2]), f3 = unpk(acc[q][3]);
                *(float4*)(wrH + q * 16 * XSTR) =
                    make_float4(fmaxf(f0.x, 0.f), fmaxf(f0.y, 0.f),
                                fmaxf(f1.x, 0.f), fmaxf(f1.y, 0.f));
                *(float4*)(wrH + q * 16 * XSTR + 32) =
                    make_float4(fmaxf(f2.x, 0.f), fmaxf(f2.y, 0.f),
                                fmaxf(f3.x, 0.f), fmaxf(f3.y, 0.f));
            }
        }
        __syncwarp();   // h exchange is warp-local

        // ---- step3: net += relu(h) @ W1 + b1 ----
        {
            ulonglong2 bA = *(const ulonglong2*)(sm + OFF_B1 + i * 64 + og * 4);
            ulonglong2 bB = *(const ulonglong2*)(sm + OFF_B1 + i * 64 + og * 4 + 32);
            #pragma unroll
            for (int q = 0; q < 8; q++) {
                ulonglong2 a = *(const ulonglong2*)(wrN + q * 16 * XSTR);
                ulonglong2 b = *(const ulonglong2*)(wrN + q * 16 * XSTR + 32);
                acc[q][0] = a.x; acc[q][1] = a.y; acc[q][2] = b.x; acc[q][3] = b.y;
                add2(acc[q][0], bA.x); add2(acc[q][1], bA.y);
                add2(acc[q][2], bB.x); add2(acc[q][3], bB.y);
            }
            mm64g(acc, xh, W1_g, false);
            #pragma unroll
            for (int q = 0; q < 8; q++) {
                ulonglong2 s0, s1;
                s0.x = acc[q][0]; s0.y = acc[q][1]; s1.x = acc[q][2]; s1.y = acc[q][3];
                *(ulonglong2*)(wrN + q * 16 * XSTR)      = s0;
                *(ulonglong2*)(wrN + q * 16 * XSTR + 32) = s1;
            }
        }
        __syncwarp();   // next block's step1 reads net (warp-local)
    }

    __syncthreads();   // barrier #2: epilogue reads rows across warps

    // ---- out = relu(net) @ fc_out_W + fc_out_b ; one point per thread ----
    {
        ull o[6];
        const ull* ob = (const ull*)(sm + OFF_OB);
        #pragma unroll
        for (int j = 0; j < 6; j++) o[j] = ob[j];
        const float* xr = NETB + tid * XSTR;
        #pragma unroll 2
        for (int kk = 0; kk < 64; kk += 4) {
            float xa[4];
            *(float4*)xa = *(const float4*)(xr + kk);
            #pragma unroll
            for (int d = 0; d < 4; d++) {
                ull xd = dup2(fmaxf(xa[d], 0.f));
                const ull* wr = (const ull*)(sm + OFF_OW + (kk + d) * 12);
                #pragma unroll
                for (int j = 0; j < 6; j++) fma2(o[j], xd, wr[j]);
            }
        }
        float2 f0 = unpk(o[0]), f1 = unpk(o[1]), f2 = unpk(o[2]);
        float2 f3 = unpk(o[3]), f4 = unpk(o[4]), f5 = unpk(o[5]);
        float4* dst = (float4*)(out + (size_t)(base + tid) * 12);
        dst[0] = make_float4(f0.x, f0.y, f1.x, f1.y);
        dst[1] = make_float4(f2.x, f2.y, f3.x, f3.y);
        dst[2] = make_float4(f4.x, f4.y, f5.x, f5.y);
    }
}

extern "C" void kernel_launch(void* const* d_in, const int* in_sizes, int n_in,
                              void* d_out, int out_size) {
    const float* p        = (const float*)d_in[0];
    const float* c        = (const float*)d_in[1];
    const float* tf       = (const float*)d_in[2];
    const float* fc_p_W   = (const float*)d_in[3];
    const float* fc_p_b   = (const float*)d_in[4];
    const float* fc_c_W   = (const float*)d_in[5];
    const float* fc_c_b   = (const float*)d_in[6];
    const float* blk0_W   = (const float*)d_in[7];
    const float* blk0_b   = (const float*)d_in[8];
    const float* blk1_W   = (const float*)d_in[9];
    const float* blk1_b   = (const float*)d_in[10];
    const float* fc_out_W = (const float*)d_in[11];
    const float* fc_out_b = (const float*)d_in[12];
    float* out = (float*)d_out;

    cudaFuncSetAttribute(mlp_kernel, cudaFuncAttributeMaxDynamicSharedMemorySize, SM_BYTES);

    cond_kernel<<<8 * NBLK, 256>>>(tf, fc_c_W, fc_c_b);

    int grid = TOT / PTS;   // 3125 CTAs
    mlp_kernel<<<grid, THR, SM_BYTES>>>(p, c, fc_p_W, fc_p_b, fc_c_W,
                                        blk0_W, blk0_b, blk1_W, blk1_b,
                                        fc_out_W, fc_out_b, out);
}

// round 12
// speedup vs baseline: 1.0479x; 1.0462x over previous
#include <cuda_runtime.h>
#include <cstdint>

#define TOT    400000
#define NPTS   50000
#define NBLK   5
#define PTS    128          // points per CTA
#define THR    128          // threads per CTA
#define XSTR   68           // activation row stride (floats)

typedef unsigned long long ull;

// Per-batch conditioning: cond[b][i][h] = task_feature[b] @ fc_c_W[i][64:576,:] + fc_c_b[i]
__device__ float g_cond[8 * NBLK * 64];

// ---------- packed f32x2 helpers ----------
__device__ __forceinline__ ull dup2(float x) {
    ull r; asm("mov.b64 %0, {%1, %1};" : "=l"(r) : "f"(x)); return r;
}
__device__ __forceinline__ float2 unpk(ull a) {
    float2 f; asm("mov.b64 {%0, %1}, %2;" : "=f"(f.x), "=f"(f.y) : "l"(a)); return f;
}
__device__ __forceinline__ void fma2(ull &a, ull x, ull w) {
    asm("fma.rn.f32x2 %0, %1, %2, %0;" : "+l"(a) : "l"(x), "l"(w));
}
__device__ __forceinline__ void add2(ull &a, ull b) {
    asm("add.rn.f32x2 %0, %0, %1;" : "+l"(a) : "l"(b));
}

// ---------- cp.async helpers ----------
__device__ __forceinline__ void cpa16(uint32_t dst, const float* src) {
    asm volatile("cp.async.cg.shared.global [%0], [%1], 16;" :: "r"(dst), "l"(src));
}
__device__ __forceinline__ void cpa_commit() {
    asm volatile("cp.async.commit_group;");
}
template<int N> __device__ __forceinline__ void cpa_wait() {
    asm volatile("cp.async.wait_group %0;" :: "n"(N));
}

// 16KB weight tile (64x64 f32): 8 x 16B per thread (128 threads)
__device__ __forceinline__ void load_w16(float* dst, const float* src, int tid) {
    uint32_t d = (uint32_t)__cvta_generic_to_shared(dst);
    #pragma unroll
    for (int t = 0; t < 8; t++) {
        int w = tid + t * THR;
        cpa16(d + w * 16, src + w * 4);
    }
}
// 32KB codes -> X (128 rows x XSTR): 16 x 16B per thread
__device__ __forceinline__ void load_codes(float* X, const float* src, int tid) {
    uint32_t d = (uint32_t)__cvta_generic_to_shared(X);
    #pragma unroll
    for (int t = 0; t < 16; t++) {
        int w = tid + t * THR;
        int pt = w >> 4, e = w & 15;
        cpa16(d + (pt * XSTR + e * 4) * 4, src + w * 4);
    }
}

// ---------- shared layout (float offsets) ----------
#define OFF_WA    0        // 4096
#define OFF_WB    4096     // 4096
#define OFF_NET   8192     // 128*68 = 8704
#define OFF_X     16896    // 8704 (codes OR relu(h))
#define OFF_OW    25600    // 768
#define OFF_OB    26368    // 16 (12 + pad)
#define OFF_PW    26384    // 192
#define OFF_PB    26576    // 64
#define OFF_CND   26640    // 2 * 320 (cond rows for this CTA's <=2 batches)
#define OFF_B0    27280    // 5*64
#define OFF_B1    27600    // 5*64
#define SM_FLOATS 27920
#define SM_BYTES  (SM_FLOATS * 4)   // 111680 B -> 2 CTAs/SM

// ---------- conditioning precompute ----------
__global__ void cond_kernel(const float* __restrict__ tf,
                            const float* __restrict__ fc_c_W,
                            const float* __restrict__ fc_c_b) {
    int bi = blockIdx.x;          // b*5 + i
    int b  = bi / NBLK, i = bi % NBLK;
    int h  = threadIdx.x & 63, g = threadIdx.x >> 6;
    const float* W = fc_c_W + (size_t)i * 576 * 64 + 64 * 64 + h;
    const float* t = tf + b * 512;
    float acc = 0.f;
    int k0 = g * 128;
    #pragma unroll 8
    for (int k = k0; k < k0 + 128; k++) acc += t[k] * W[(size_t)k * 64];
    __shared__ float red[256];
    red[threadIdx.x] = acc;
    __syncthreads();
    if (g == 0) {
        float s = red[h] + red[h + 64] + red[h + 128] + red[h + 192] + fc_c_b[i * 64 + h];
        g_cond[bi * 64 + h] = s;
    }
}

// GEMM microtile: 8 points (rows pg+16q) x 8 cols ({og*4..+3}, {32+og*4..+3}).
// x double-buffered one kk-chunk ahead; FMAs ordered j-OUTER / q-INNER so the
// weight operand repeats in 8 consecutive FFMA2s -> operand-reuse cache hit
// -> RF banking rt=2 instead of rt=3.
__device__ __forceinline__ void mm64(ull acc[8][4], const float* __restrict__ xb,
                                     const float* __restrict__ Wt, bool relu_x) {
    float xa[2][8][4];
    #pragma unroll
    for (int q = 0; q < 8; q++)
        *(float4*)xa[0][q] = *(const float4*)(xb + q * 16 * XSTR);
    #pragma unroll 2
    for (int kc = 0; kc < 16; kc++) {
        const int cur = kc & 1, nxt = cur ^ 1;
        if (kc < 15) {
            #pragma unroll
            for (int q = 0; q < 8; q++)
                *(float4*)xa[nxt][q] = *(const float4*)(xb + q * 16 * XSTR + (kc + 1) * 4);
        }
        #pragma unroll
        for (int d = 0; d < 4; d++) {
            ulonglong2 wA = *(const ulonglong2*)(Wt + (kc * 4 + d) * 64);
            ulonglong2 wB = *(const ulonglong2*)(Wt + (kc * 4 + d) * 64 + 32);
            ull xd[8];
            #pragma unroll
            for (int q = 0; q < 8; q++) {
                float xv = xa[cur][q][d];
                if (relu_x) xv = fmaxf(xv, 0.f);
                xd[q] = dup2(xv);
            }
            #pragma unroll
            for (int q = 0; q < 8; q++) fma2(acc[q][0], xd[q], wA.x);
            #pragma unroll
            for (int q = 0; q < 8; q++) fma2(acc[q][1], xd[q], wA.y);
            #pragma unroll
            for (int q = 0; q < 8; q++) fma2(acc[q][2], xd[q], wB.x);
            #pragma unroll
            for (int q = 0; q < 8; q++) fma2(acc[q][3], xd[q], wB.y);
        }
    }
}

__global__ __launch_bounds__(THR, 2)
void mlp_kernel(const float* __restrict__ p, const float* __restrict__ c,
                const float* __restrict__ fc_p_W, const float* __restrict__ fc_p_b,
                const float* __restrict__ fc_c_W,
                const float* __restrict__ blk0_W, const float* __restrict__ blk0_b,
                const float* __restrict__ blk1_W, const float* __restrict__ blk1_b,
                const float* __restrict__ fc_out_W, const float* __restrict__ fc_out_b,
                float* __restrict__ out) {
    extern __shared__ float sm[];
    const int tid = threadIdx.x;
    const int og  = tid & 7;          // cols og*4..+3 and 32+og*4..+3
    const int pg  = tid >> 3;         // rows pg + 16q, q=0..7
    const int base = blockIdx.x * PTS;
    const int bA_id = base / NPTS;
    const int bB_id = (base + PTS - 1) / NPTS;

    float* WA   = sm + OFF_WA;
    float* WB   = sm + OFF_WB;
    float* NETB = sm + OFF_NET;
    float* X    = sm + OFF_X;

    // prologue async: Wc_0 -> WA (group), codes -> X (group)
    load_w16(WA, fc_c_W, tid); cpa_commit();
    load_codes(X, c + (size_t)base * 64, tid); cpa_commit();

    // one-time small operands -> smem (strided over full range; THR=128)
    for (int w = tid; w < 768; w += THR) sm[OFF_OW + w] = fc_out_W[w];
    if (tid < 16) sm[OFF_OB + tid] = (tid < 12) ? fc_out_b[tid] : 0.f;
    for (int w = tid; w < 192; w += THR) sm[OFF_PW + w] = fc_p_W[w];
    for (int w = tid; w < 64; w += THR) sm[OFF_PB + w] = fc_p_b[w];
    for (int w = tid; w < 640; w += THR) {          // cond rows for batches bA/bB
        int sel = w / 320, r = w % 320;
        sm[OFF_CND + w] = g_cond[(sel ? bB_id : bA_id) * 320 + r];
    }
    for (int w = tid; w < 320; w += THR) {
        sm[OFF_B0 + w] = blk0_b[w];
        sm[OFF_B1 + w] = blk1_b[w];
    }
    __syncthreads();   // smem params visible (cp.async groups still in flight)

    float* wrN = NETB + pg * XSTR + og * 4;      // own net tile
    float* wrX = X    + pg * XSTR + og * 4;      // own h tile
    const float* xb = X    + pg * XSTR;
    const float* nb = NETB + pg * XSTR;

    // per-row cond smem offsets
    int cnd[8];
    #pragma unroll
    for (int q = 0; q < 8; q++) {
        int sel = ((base + pg + q * 16) / NPTS == bB_id) ? 1 : 0;
        cnd[q] = OFF_CND + sel * 320 + og * 4;
    }

    // ---- p-layer: net0 = p @ Wp + bp -> NETB (own tile) ----
    {
        ulonglong2 bA = *(const ulonglong2*)(sm + OFF_PB + og * 4);
        ulonglong2 bB = *(const ulonglong2*)(sm + OFF_PB + og * 4 + 32);
        ulonglong2 w[3][2];
        #pragma unroll
        for (int e = 0; e < 3; e++) {
            w[e][0] = *(const ulonglong2*)(sm + OFF_PW + e * 64 + og * 4);
            w[e][1] = *(const ulonglong2*)(sm + OFF_PW + e * 64 + og * 4 + 32);
        }
        #pragma unroll
        for (int q = 0; q < 8; q++) {
            int pt = base + pg + q * 16;
            ull a0 = bA.x, a1 = bA.y, a2 = bB.x, a3 = bB.y;
            #pragma unroll
            for (int e = 0; e < 3; e++) {
                ull xd = dup2(__ldg(p + (size_t)pt * 3 + e));
                fma2(a0, xd, w[e][0].x); fma2(a1, xd, w[e][0].y);
                fma2(a2, xd, w[e][1].x); fma2(a3, xd, w[e][1].y);
            }
            ulonglong2 s0, s1; s0.x = a0; s0.y = a1; s1.x = a2; s1.y = a3;
            *(ulonglong2*)(wrN + q * 16 * XSTR)      = s0;
            *(ulonglong2*)(wrN + q * 16 * XSTR + 32) = s1;
        }
    }

    for (int i = 0; i < NBLK; i++) {
        float* Wcur = (i & 1) ? WB : WA;
        float* Woth = (i & 1) ? WA : WB;

        if (i > 0) { load_codes(X, c + (size_t)base * 64, tid); cpa_commit(); }
        load_w16(Woth, blk0_W + (size_t)i * 4096, tid); cpa_commit();
        cpa_wait<1>();            // Wc_i + codes done; W0 still in flight
        __syncthreads();

        ull acc[8][4];
        // ---- step1: net = net + cond + c @ Wc ----
        #pragma unroll
        for (int q = 0; q < 8; q++) {
            ulonglong2 a = *(const ulonglong2*)(wrN + q * 16 * XSTR);
            ulonglong2 b = *(const ulonglong2*)(wrN + q * 16 * XSTR + 32);
            ulonglong2 c0 = *(const ulonglong2*)(sm + cnd[q] + i * 64);
            ulonglong2 c1 = *(const ulonglong2*)(sm + cnd[q] + i * 64 + 32);
            acc[q][0] = a.x; acc[q][1] = a.y; acc[q][2] = b.x; acc[q][3] = b.y;
            add2(acc[q][0], c0.x); add2(acc[q][1], c0.y);
            add2(acc[q][2], c1.x); add2(acc[q][3], c1.y);
        }
        mm64(acc, xb, Wcur + og * 4, false);
        #pragma unroll
        for (int q = 0; q < 8; q++) {
            ulonglong2 s0, s1;
            s0.x = acc[q][0]; s0.y = acc[q][1]; s1.x = acc[q][2]; s1.y = acc[q][3];
            *(ulonglong2*)(wrN + q * 16 * XSTR)      = s0;
            *(ulonglong2*)(wrN + q * 16 * XSTR + 32) = s1;
        }
        cpa_wait<0>();            // W0 arrived
        __syncthreads();

        // ---- step2: h = relu(net) @ W0 + b0 ; relu(h) -> X ----
        load_w16(Wcur, blk1_W + (size_t)i * 4096, tid); cpa_commit();  // W1 prefetch
        {
            ulonglong2 bA = *(const ulonglong2*)(sm + OFF_B0 + i * 64 + og * 4);
            ulonglong2 bB = *(const ulonglong2*)(sm + OFF_B0 + i * 64 + og * 4 + 32);
            #pragma unroll
            for (int q = 0; q < 8; q++) {
                acc[q][0] = bA.x; acc[q][1] = bA.y; acc[q][2] = bB.x; acc[q][3] = bB.y;
            }
            mm64(acc, nb, Woth + og * 4, true);
            #pragma unroll
            for (int q = 0; q < 8; q++) {
                float2 f0 = unpk(acc[q][0]), f1 = unpk(acc[q][1]);
                float2 f2 = unpk(acc[q][2]), f3 = unpk(acc[q][3]);
                *(float4*)(wrX + q * 16 * XSTR) =
                    make_float4(fmaxf(f0.x, 0.f), fmaxf(f0.y, 0.f),
                                fmaxf(f1.x, 0.f), fmaxf(f1.y, 0.f));
                *(float4*)(wrX + q * 16 * XSTR + 32) =
                    make_float4(fmaxf(f2.x, 0.f), fmaxf(f2.y, 0.f),
                                fmaxf(f3.x, 0.f), fmaxf(f3.y, 0.f));
            }
        }
        cpa_wait<0>();            // W1 arrived
        __syncthreads();

        // ---- step3: net += relu(h) @ W1 + b1 ----
        if (i < NBLK - 1) { load_w16(Woth, fc_c_W + (size_t)(i + 1) * 576 * 64, tid); cpa_commit(); }
        {
            ulonglong2 bA = *(const ulonglong2*)(sm + OFF_B1 + i * 64 + og * 4);
            ulonglong2 bB = *(const ulonglong2*)(sm + OFF_B1 + i * 64 + og * 4 + 32);
            #pragma unroll
            for (int q = 0; q < 8; q++) {
                ulonglong2 a = *(const ulonglong2*)(wrN + q * 16 * XSTR);
                ulonglong2 b = *(const ulonglong2*)(wrN + q * 16 * XSTR + 32);
                acc[q][0] = a.x; acc[q][1] = a.y; acc[q][2] = b.x; acc[q][3] = b.y;
                add2(acc[q][0], bA.x); add2(acc[q][1], bA.y);
                add2(acc[q][2], bB.x); add2(acc[q][3], bB.y);
            }
            mm64(acc, xb, Wcur + og * 4, false);
            #pragma unroll
            for (int q = 0; q < 8; q++) {
                ulonglong2 s0, s1;
                s0.x = acc[q][0]; s0.y = acc[q][1]; s1.x = acc[q][2]; s1.y = acc[q][3];
                *(ulonglong2*)(wrN + q * 16 * XSTR)      = s0;
                *(ulonglong2*)(wrN + q * 16 * XSTR + 32) = s1;
            }
        }
        __syncthreads();
    }

    // ---- out = relu(net) @ fc_out_W + fc_out_b ; one point per thread ----
    {
        ull o[6];
        const ull* ob = (const ull*)(sm + OFF_OB);
        #pragma unroll
        for (int j = 0; j < 6; j++) o[j] = ob[j];
        const float* xr = NETB + tid * XSTR;
        #pragma unroll 2
        for (int kk = 0; kk < 64; kk += 4) {
            float xa[4];
            *(float4*)xa = *(const float4*)(xr + kk);
            #pragma unroll
            for (int d = 0; d < 4; d++) {
                ull xd = dup2(fmaxf(xa[d], 0.f));
                const ull* wr = (const ull*)(sm + OFF_OW + (kk + d) * 12);
                #pragma unroll
                for (int j = 0; j < 6; j++) fma2(o[j], xd, wr[j]);
            }
        }
        float2 f0 = unpk(o[0]), f1 = unpk(o[1]), f2 = unpk(o[2]);
        float2 f3 = unpk(o[3]), f4 = unpk(o[4]), f5 = unpk(o[5]);
        float4* dst = (float4*)(out + (size_t)(base + tid) * 12);
        dst[0] = make_float4(f0.x, f0.y, f1.x, f1.y);
        dst[1] = make_float4(f2.x, f2.y, f3.x, f3.y);
        dst[2] = make_float4(f4.x, f4.y, f5.x, f5.y);
    }
}

extern "C" void kernel_launch(void* const* d_in, const int* in_sizes, int n_in,
                              void* d_out, int out_size) {
    const float* p        = (const float*)d_in[0];
    const float* c        = (const float*)d_in[1];
    const float* tf       = (const float*)d_in[2];
    const float* fc_p_W   = (const float*)d_in[3];
    const float* fc_p_b   = (const float*)d_in[4];
    const float* fc_c_W   = (const float*)d_in[5];
    const float* fc_c_b   = (const float*)d_in[6];
    const float* blk0_W   = (const float*)d_in[7];
    const float* blk0_b   = (const float*)d_in[8];
    const float* blk1_W   = (const float*)d_in[9];
    const float* blk1_b   = (const float*)d_in[10];
    const float* fc_out_W = (const float*)d_in[11];
    const float* fc_out_b = (const float*)d_in[12];
    float* out = (float*)d_out;

    cudaFuncSetAttribute(mlp_kernel, cudaFuncAttributeMaxDynamicSharedMemorySize, SM_BYTES);

    cond_kernel<<<8 * NBLK, 256>>>(tf, fc_c_W, fc_c_b);

    int grid = TOT / PTS;   // 3125 CTAs
    mlp_kernel<<<grid, THR, SM_BYTES>>>(p, c, fc_p_W, fc_p_b, fc_c_W,
                                        blk0_W, blk0_b, blk1_W, blk1_b,
                                        fc_out_W, fc_out_b, out);
}